// round 13
// baseline (speedup 1.0000x reference)
#include <cuda_runtime.h>
#include <cuda_bf16.h>

#define BATCH 8
#define SEQT 2048
#define CDIM 1024
#define HDIM 128
#define BT (BATCH * SEQT)   // 16384 tokens

// ---------------- device scratch (16B aligned) ----------------
__device__ __align__(16) __nv_bfloat16 g_whi[3][CDIM * HDIM];  // [c][h]
__device__ __align__(16) __nv_bfloat16 g_wlo[3][CDIM * HDIM];
__device__ __align__(16) __nv_bfloat16 g_Qhi[BT * HDIM];
__device__ __align__(16) __nv_bfloat16 g_Khi[BT * HDIM];
__device__ __align__(16) __nv_bfloat16 g_Vhi[BT * HDIM];
__device__ __align__(16) __nv_bfloat16 g_Vlo[BT * HDIM];
// split-K partials: [mode][tile=(qt-16)*8+b][row][dim]
__device__ __align__(16) float  g_part[2 * 128 * 64 * 128];   // 8 MB
__device__ __align__(16) float2 g_ml[2 * 128 * 64];

// slot tables: 48 slots (32 split halves + 16 unsplit), descending length
__device__ const unsigned char c_slot_qt[48] = {
    31,31,30,15,30,29,29,28,14,28,27,27,26,13,26,25,
    25,24,12,24,23,23,22,11,22,21,21,20,10,20,19,19,
    18, 9,18,17,17,16, 8,16, 7, 6, 5, 4, 3, 2, 1, 0};
__device__ const unsigned char c_slot_md[48] = {
    0,1,0,2,1,0,1,0,2,1,0,1,0,2,1,0,
    1,0,2,1,0,1,0,2,1,0,1,0,2,1,0,1,
    0,2,1,0,1,0,2,1,2,2,2,2,2,2,2,2};

// ---------------- helpers ----------------
__device__ __forceinline__ unsigned smem_u32(const void* p) {
    unsigned a;
    asm("{ .reg .u64 t; cvta.to.shared.u64 t, %1; cvt.u32.u64 %0, t; }"
        : "=r"(a) : "l"(p));
    return a;
}
__device__ __forceinline__ void ldsm4(unsigned* r, unsigned a) {
    asm volatile("ldmatrix.sync.aligned.m8n8.x4.shared.b16 {%0,%1,%2,%3}, [%4];"
                 : "=r"(r[0]), "=r"(r[1]), "=r"(r[2]), "=r"(r[3]) : "r"(a));
}
__device__ __forceinline__ void ldsm4t(unsigned* r, unsigned a) {
    asm volatile("ldmatrix.sync.aligned.m8n8.x4.trans.shared.b16 {%0,%1,%2,%3}, [%4];"
                 : "=r"(r[0]), "=r"(r[1]), "=r"(r[2]), "=r"(r[3]) : "r"(a));
}
__device__ __forceinline__ void mma16816(float* d, const unsigned* a, const unsigned* b) {
    asm volatile(
        "mma.sync.aligned.m16n8k16.row.col.f32.bf16.bf16.f32 "
        "{%0,%1,%2,%3}, {%4,%5,%6,%7}, {%8,%9}, {%0,%1,%2,%3};"
        : "+f"(d[0]), "+f"(d[1]), "+f"(d[2]), "+f"(d[3])
        : "r"(a[0]), "r"(a[1]), "r"(a[2]), "r"(a[3]), "r"(b[0]), "r"(b[1]));
}
__device__ __forceinline__ unsigned pack2(__nv_bfloat16 first, __nv_bfloat16 second) {
    return (unsigned)__bfloat16_as_ushort(first) |
           ((unsigned)__bfloat16_as_ushort(second) << 16);
}
__device__ __forceinline__ unsigned pack2f(float first, float second) {
    return pack2(__float2bfloat16(first), __float2bfloat16(second));
}
__device__ __forceinline__ void cp16(unsigned dst, const void* src) {
    asm volatile("cp.async.cg.shared.global [%0], [%1], 16;"
                 :: "r"(dst), "l"(src));
}
#define CP_COMMIT() asm volatile("cp.async.commit_group;")
#define CP_WAIT0()  asm volatile("cp.async.wait_group 0;" ::: "memory")
#define CP_WAIT1()  asm volatile("cp.async.wait_group 1;" ::: "memory")

// ---------------- prep: split W fp32 -> bf16 hi/lo ----------------
__global__ __launch_bounds__(256) void split_w_kernel(
    const float* __restrict__ Wq, const float* __restrict__ Wk,
    const float* __restrict__ Wv) {
    int idx = blockIdx.x * 256 + threadIdx.x;
    int mat = idx >> 17;
    int r   = idx & 131071;
    const float* W = (mat == 0) ? Wq : (mat == 1) ? Wk : Wv;
    float v = W[r];
    __nv_bfloat16 hi = __float2bfloat16(v);
    g_whi[mat][r] = hi;
    g_wlo[mat][r] = __float2bfloat16(v - __bfloat162float(hi));
}

// ---------------- fused QKV projection: FM=64, 512 threads ----------------
// 16 warps = 4m x 4n; W chunk loaded once serves 64 tokens (halved L2 traffic).
#define FM 64
#define FK 32
#define F_XF(s)    ((s) * 8192)                          // 64 x 128B fp32
#define F_W(s, m)  (16384 + (s) * 32768 + (m) * 8192)    // 4 x 32 x 256B bf16
#define F_XH 81920                                       // 64 rows stride 80B
#define F_XL 87040
#define F_SMEM 92160
#define SWB(row, unit) (((row) << 8) + ((((unit) ^ ((row) & 7))) << 4))

__global__ __launch_bounds__(512, 1) void fused_proj_kernel(
    const float* __restrict__ x,
    const float* __restrict__ bq, const float* __restrict__ bk,
    const float* __restrict__ bv) {
    extern __shared__ char smc[];
    const unsigned sb = smem_u32(smc);
    const int tid = threadIdx.x;
    const int w   = tid >> 5;          // 0..15
    const int l   = tid & 31;
    const int wi  = w >> 2;            // m-block 0..3 (16 rows each)
    const int wj  = w & 3;             // n-quarter 0..3 (32 cols)
    const int mi  = wi * 16;
    const int m0  = blockIdx.x * FM;

    const __nv_bfloat16* wsrc[4] = {g_whi[0], g_whi[1], g_whi[2], g_wlo[2]};
    const int xrow = tid >> 3, xq = tid & 7;   // 64 rows x 8 units = 512 slots

    auto issue_loads = [&](int ch, int s) {
        const int k0 = ch * FK;
        cp16(sb + F_XF(s) + xrow * 128 + xq * 16,
             x + (size_t)(m0 + xrow) * CDIM + k0 + xq * 4);
#pragma unroll
        for (int t = 0; t < 4; t++) {
            int u = tid + t * 512;               // 0..2047
            int m = u >> 9;
            int r = (u >> 4) & 31;
            int q = u & 15;
            cp16(sb + F_W(s, m) + SWB(r, q),
                 wsrc[m] + (size_t)(k0 + r) * HDIM + q * 8);
        }
        CP_COMMIT();
    };

    float acc[3][4][4];
#pragma unroll
    for (int m = 0; m < 3; m++)
#pragma unroll
        for (int t = 0; t < 4; t++)
#pragma unroll
            for (int r = 0; r < 4; r++) acc[m][t][r] = 0.0f;

    issue_loads(0, 0);

    for (int ch = 0; ch < 32; ch++) {
        const int s = ch & 1;
        CP_WAIT0();
        __syncthreads();   // barA: stage s landed everywhere

        if (ch + 1 < 32) issue_loads(ch + 1, s ^ 1);

        // convert x fp32 -> bf16 hi/lo (1 float4/thread covers 64x32)
        {
            float4 v = *reinterpret_cast<const float4*>(
                smc + F_XF(s) + xrow * 128 + xq * 16);
            __nv_bfloat16 h0 = __float2bfloat16(v.x), h1 = __float2bfloat16(v.y);
            __nv_bfloat16 h2 = __float2bfloat16(v.z), h3 = __float2bfloat16(v.w);
            uint2 hv, lv;
            hv.x = pack2(h0, h1);
            hv.y = pack2(h2, h3);
            lv.x = pack2f(v.x - __bfloat162float(h0), v.y - __bfloat162float(h1));
            lv.y = pack2f(v.z - __bfloat162float(h2), v.w - __bfloat162float(h3));
            *reinterpret_cast<uint2*>(smc + F_XH + xrow * 80 + xq * 8) = hv;
            *reinterpret_cast<uint2*>(smc + F_XL + xrow * 80 + xq * 8) = lv;
        }
        __syncthreads();   // barB: conversion visible

#pragma unroll
        for (int ks = 0; ks < 2; ks++) {
            unsigned ah[4], al[4];
            unsigned a_off = (mi + (l & 15)) * 80 + (ks * 2 + (l >> 4)) * 16;
            ldsm4(ah, sb + F_XH + a_off);
            ldsm4(al, sb + F_XL + a_off);
            const int brow = ks * 16 + (l & 15);
#pragma unroll
            for (int m = 0; m < 3; m++) {
#pragma unroll
                for (int nt2 = 0; nt2 < 2; nt2++) {
                    unsigned bh[4];
                    unsigned unit = wj * 4 + nt2 * 2 + (l >> 4);
                    ldsm4t(bh, sb + F_W(s, m) + SWB(brow, unit));
                    mma16816(acc[m][2 * nt2],     ah, bh);
                    mma16816(acc[m][2 * nt2 + 1], ah, bh + 2);
                    mma16816(acc[m][2 * nt2],     al, bh);
                    mma16816(acc[m][2 * nt2 + 1], al, bh + 2);
                }
            }
#pragma unroll
            for (int nt2 = 0; nt2 < 2; nt2++) {
                unsigned bl[4];
                unsigned unit = wj * 4 + nt2 * 2 + (l >> 4);
                ldsm4t(bl, sb + F_W(s, 3) + SWB(brow, unit));
                mma16816(acc[2][2 * nt2],     ah, bl);
                mma16816(acc[2][2 * nt2 + 1], ah, bl + 2);
            }
        }
    }

    const int r0 = m0 + mi + (l >> 2);
    const int r1 = r0 + 8;
    const float* biases[3] = {bq, bk, bv};
#pragma unroll
    for (int m = 0; m < 3; m++) {
        __nv_bfloat16* ohi = (m == 0) ? g_Qhi : (m == 1) ? g_Khi : g_Vhi;
#pragma unroll
        for (int nt = 0; nt < 4; nt++) {
            int c = wj * 32 + nt * 8 + (l & 3) * 2;
            float b0 = biases[m][c], b1 = biases[m][c + 1];
            float vals[4] = {acc[m][nt][0] + b0, acc[m][nt][1] + b1,
                             acc[m][nt][2] + b0, acc[m][nt][3] + b1};
            int rows[4] = {r0, r0, r1, r1};
            int cols[4] = {c, c + 1, c, c + 1};
#pragma unroll
            for (int e = 0; e < 4; e++) {
                size_t off = (size_t)rows[e] * HDIM + cols[e];
                __nv_bfloat16 h = __float2bfloat16(vals[e]);
                ohi[off] = h;
                if (m == 2)   // only V keeps a lo tail (output path)
                    g_Vlo[off] = __float2bfloat16(vals[e] - __bfloat162float(h));
            }
        }
    }
}

// ---------------- flash attention: split-K, QK single-bf16 ----------------
#define S_QH 0
#define S_KH 16384
#define S_VH 32768
#define S_VL 49152
#define S_PH 65536
#define S_PL 73728
#define S_XB 81920
#define A_SMEM 82944
#define SWP(row, unit) (((row) << 7) + ((((unit) ^ ((row) & 7))) << 4))

__global__ __launch_bounds__(256, 2) void attn_kernel(float* __restrict__ out) {
    extern __shared__ char smc[];
    const unsigned sb = smem_u32(smc);
    const int tid = threadIdx.x;
    const int w   = tid >> 5;          // 0..7
    const int l   = tid & 31;
    const int wi  = w >> 1;            // m-block 0..3
    const int wj  = w & 1;             // n-half 0..1
    const int mi  = wi * 16;

    const int bid  = blockIdx.x;
    const int slot = bid >> 3;
    const int b    = bid & 7;
    const int qt   = c_slot_qt[slot];
    const int md   = c_slot_md[slot];  // 0=lower half, 1=upper half, 2=full
    const int h    = (qt + 2) >> 1;
    const int kb   = (md == 1) ? h : 0;
    const int ke   = (md == 0) ? (h - 1) : qt;
    const int q0   = qt * 64;
    const float scale = 0.03125f;      // 1024^-0.5

    const int lrow = (tid >> 4);
    const int lq   = tid & 15;

    // prologue: group0 = Q + K(kb); group1 = V(kb)
#pragma unroll
    for (int t = 0; t < 4; t++) {
        int row = lrow + t * 16;
        size_t gq = (size_t)(b * SEQT + q0 + row) * HDIM + lq * 8;
        size_t gk = (size_t)(b * SEQT + kb * 64 + row) * HDIM + lq * 8;
        cp16(sb + S_QH + SWB(row, lq), g_Qhi + gq);
        cp16(sb + S_KH + SWB(row, lq), g_Khi + gk);
    }
    CP_COMMIT();
#pragma unroll
    for (int t = 0; t < 4; t++) {
        int row = lrow + t * 16;
        size_t g = (size_t)(b * SEQT + kb * 64 + row) * HDIM + lq * 8;
        cp16(sb + S_VH + SWB(row, lq), g_Vhi + g);
        cp16(sb + S_VL + SWB(row, lq), g_Vlo + g);
    }
    CP_COMMIT();

    float m0_ = -1e30f, m1_ = -1e30f, l0_ = 0.0f, l1_ = 0.0f;
    float O[8][4];
#pragma unroll
    for (int t = 0; t < 8; t++)
#pragma unroll
        for (int r = 0; r < 4; r++) O[t][r] = 0.0f;

    const int row0 = mi + (l >> 2);
    const int row1 = row0 + 8;
    const int r0g  = q0 + row0;
    const int r1g  = r0g + 8;

    for (int kt = kb; kt <= ke; kt++) {
        const int k0 = kt * 64;
        CP_WAIT1();
        __syncthreads();   // (A) K visible

        float sacc[4][4];
#pragma unroll
        for (int t = 0; t < 4; t++)
#pragma unroll
            for (int r = 0; r < 4; r++) sacc[t][r] = 0.0f;

#pragma unroll
        for (int ks = 0; ks < 8; ks++) {
            unsigned ah[4];
            unsigned a_off = SWB(mi + (l & 15), ks * 2 + (l >> 4));
            ldsm4(ah, sb + S_QH + a_off);
#pragma unroll
            for (int nt2 = 0; nt2 < 2; nt2++) {
                unsigned bh[4];
                int brow = 32 * wj + nt2 * 16 + ((l >> 4) << 3) + (l & 7);
                unsigned b_off = SWB(brow, ks * 2 + ((l >> 3) & 1));
                ldsm4(bh, sb + S_KH + b_off);
                mma16816(sacc[2 * nt2],     ah, bh);
                mma16816(sacc[2 * nt2 + 1], ah, bh + 2);
            }
        }

        const bool mask_it = (kt == qt);
#pragma unroll
        for (int nt = 0; nt < 4; nt++) {
            int cg = k0 + 32 * wj + nt * 8 + (l & 3) * 2;
            float s0 = sacc[nt][0] * scale, s1 = sacc[nt][1] * scale;
            float s2 = sacc[nt][2] * scale, s3 = sacc[nt][3] * scale;
            if (mask_it) {
                if (cg     > r0g) s0 = -1e30f;
                if (cg + 1 > r0g) s1 = -1e30f;
                if (cg     > r1g) s2 = -1e30f;
                if (cg + 1 > r1g) s3 = -1e30f;
            }
            sacc[nt][0] = s0; sacc[nt][1] = s1; sacc[nt][2] = s2; sacc[nt][3] = s3;
        }
        float mt0 = -1e30f, mt1 = -1e30f;
#pragma unroll
        for (int nt = 0; nt < 4; nt++) {
            mt0 = fmaxf(mt0, fmaxf(sacc[nt][0], sacc[nt][1]));
            mt1 = fmaxf(mt1, fmaxf(sacc[nt][2], sacc[nt][3]));
        }
        mt0 = fmaxf(mt0, __shfl_xor_sync(0xffffffffu, mt0, 1));
        mt0 = fmaxf(mt0, __shfl_xor_sync(0xffffffffu, mt0, 2));
        mt1 = fmaxf(mt1, __shfl_xor_sync(0xffffffffu, mt1, 1));
        mt1 = fmaxf(mt1, __shfl_xor_sync(0xffffffffu, mt1, 2));

        float ls0 = 0.0f, ls1 = 0.0f;
#pragma unroll
        for (int nt = 0; nt < 4; nt++) {
            float p0 = __expf(sacc[nt][0] - mt0);
            float p1 = __expf(sacc[nt][1] - mt0);
            float p2 = __expf(sacc[nt][2] - mt1);
            float p3 = __expf(sacc[nt][3] - mt1);
            sacc[nt][0] = p0; sacc[nt][1] = p1; sacc[nt][2] = p2; sacc[nt][3] = p3;
            ls0 += p0 + p1; ls1 += p2 + p3;
        }
        ls0 += __shfl_xor_sync(0xffffffffu, ls0, 1);
        ls0 += __shfl_xor_sync(0xffffffffu, ls0, 2);
        ls1 += __shfl_xor_sync(0xffffffffu, ls1, 1);
        ls1 += __shfl_xor_sync(0xffffffffu, ls1, 2);

        if ((l & 3) == 0) {
            *reinterpret_cast<float2*>(smc + S_XB + row0 * 16 + 8 * wj) =
                make_float2(mt0, ls0);
            *reinterpret_cast<float2*>(smc + S_XB + row1 * 16 + 8 * wj) =
                make_float2(mt1, ls1);
        }
        __syncthreads();   // (B) partials visible

        float4 x0 = *reinterpret_cast<const float4*>(smc + S_XB + row0 * 16);
        float4 x1 = *reinterpret_cast<const float4*>(smc + S_XB + row1 * 16);

        float mn0 = fmaxf(m0_, fmaxf(x0.x, x0.z));
        float mn1 = fmaxf(m1_, fmaxf(x1.x, x1.z));
        float al0 = __expf(m0_ - mn0), al1 = __expf(m1_ - mn1);
        float f00 = __expf(x0.x - mn0), f01 = __expf(x0.z - mn0);
        float f10 = __expf(x1.x - mn1), f11 = __expf(x1.z - mn1);
        l0_ = l0_ * al0 + x0.y * f00 + x0.w * f01;
        l1_ = l1_ * al1 + x1.y * f10 + x1.w * f11;
        m0_ = mn0; m1_ = mn1;
        float fme0 = wj ? f01 : f00;
        float fme1 = wj ? f11 : f10;

#pragma unroll
        for (int t = 0; t < 8; t++) {
            O[t][0] *= al0; O[t][1] *= al0; O[t][2] *= al1; O[t][3] *= al1;
        }

        CP_WAIT0();        // V(kt) landed

#pragma unroll
        for (int nt = 0; nt < 4; nt++) {
            float p00 = sacc[nt][0] * fme0, p01 = sacc[nt][1] * fme0;
            float p10 = sacc[nt][2] * fme1, p11 = sacc[nt][3] * fme1;
            __nv_bfloat16 h00 = __float2bfloat16(p00), h01 = __float2bfloat16(p01);
            __nv_bfloat16 h10 = __float2bfloat16(p10), h11 = __float2bfloat16(p11);
            int unit = 4 * wj + nt;
            unsigned o0 = SWP(row0, unit) + (l & 3) * 4;
            unsigned o1 = SWP(row1, unit) + (l & 3) * 4;
            *reinterpret_cast<unsigned*>(smc + S_PH + o0) = pack2(h00, h01);
            *reinterpret_cast<unsigned*>(smc + S_PH + o1) = pack2(h10, h11);
            *reinterpret_cast<unsigned*>(smc + S_PL + o0) =
                pack2f(p00 - __bfloat162float(h00), p01 - __bfloat162float(h01));
            *reinterpret_cast<unsigned*>(smc + S_PL + o1) =
                pack2f(p10 - __bfloat162float(h10), p11 - __bfloat162float(h11));
        }
        __syncthreads();   // (C) P + V visible

        if (kt < ke) {
            const int kn = k0 + 64;
#pragma unroll
            for (int t = 0; t < 4; t++) {
                int row = lrow + t * 16;
                size_t g = (size_t)(b * SEQT + kn + row) * HDIM + lq * 8;
                cp16(sb + S_KH + SWB(row, lq), g_Khi + g);
            }
            CP_COMMIT();
        }

#pragma unroll
        for (int ks2 = 0; ks2 < 4; ks2++) {
            unsigned ph[4], pl2[4];
            unsigned p_off = SWP(mi + (l & 15), ks2 * 2 + (l >> 4));
            ldsm4(ph,  sb + S_PH + p_off);
            ldsm4(pl2, sb + S_PL + p_off);
#pragma unroll
            for (int dt2 = 0; dt2 < 4; dt2++) {
                unsigned vh[4], vl[4];
                int vrow = ks2 * 16 + (l & 15);
                unsigned v_off = SWB(vrow, 8 * wj + dt2 * 2 + (l >> 4));
                ldsm4t(vh, sb + S_VH + v_off);
                ldsm4t(vl, sb + S_VL + v_off);
                mma16816(O[2 * dt2],     ph,  vh);
                mma16816(O[2 * dt2 + 1], ph,  vh + 2);
                mma16816(O[2 * dt2],     ph,  vl);
                mma16816(O[2 * dt2 + 1], ph,  vl + 2);
                mma16816(O[2 * dt2],     pl2, vh);
                mma16816(O[2 * dt2 + 1], pl2, vh + 2);
            }
        }
        __syncthreads();   // (D) PV reads done

        if (kt < ke) {
            const int kn = k0 + 64;
#pragma unroll
            for (int t = 0; t < 4; t++) {
                int row = lrow + t * 16;
                size_t g = (size_t)(b * SEQT + kn + row) * HDIM + lq * 8;
                cp16(sb + S_VH + SWB(row, lq), g_Vhi + g);
                cp16(sb + S_VL + SWB(row, lq), g_Vlo + g);
            }
            CP_COMMIT();
        }
    }

    if (md == 2) {
        float inv0 = 1.0f / l0_, inv1 = 1.0f / l1_;
#pragma unroll
        for (int dt = 0; dt < 8; dt++) {
            int c = 64 * wj + dt * 8 + (l & 3) * 2;
            float2 v0 = make_float2(O[dt][0] * inv0, O[dt][1] * inv0);
            float2 v1 = make_float2(O[dt][2] * inv1, O[dt][3] * inv1);
            *reinterpret_cast<float2*>(out + ((size_t)b * SEQT + r0g) * HDIM + c) = v0;
            *reinterpret_cast<float2*>(out + ((size_t)b * SEQT + r1g) * HDIM + c) = v1;
        }
    } else {
        const int tile = (qt - 16) * 8 + b;
        float* P = g_part + ((size_t)(md * 128 + tile) * 64) * 128;
#pragma unroll
        for (int dt = 0; dt < 8; dt++) {
            int c = 64 * wj + dt * 8 + (l & 3) * 2;
            *reinterpret_cast<float2*>(P + (size_t)row0 * 128 + c) =
                make_float2(O[dt][0], O[dt][1]);
            *reinterpret_cast<float2*>(P + (size_t)row1 * 128 + c) =
                make_float2(O[dt][2], O[dt][3]);
        }
        if (wj == 0 && (l & 3) == 0) {
            g_ml[(md * 128 + tile) * 64 + row0] = make_float2(m0_, l0_);
            g_ml[(md * 128 + tile) * 64 + row1] = make_float2(m1_, l1_);
        }
    }
}

// ---------------- split-K reduce (512 CTAs, 16 rows each) -------------------
__global__ __launch_bounds__(256) void reduce_kernel(float* __restrict__ out) {
    const int bid  = blockIdx.x;            // 0..511
    const int tile = bid >> 2;              // 0..127
    const int quad = bid & 3;
    const int qt = 16 + (tile >> 3);
    const int b  = tile & 7;
    const int row = quad * 16 + (threadIdx.x >> 4);   // 0..63
    const int cg  = (threadIdx.x & 15) * 8;

    float2 ml0 = g_ml[tile * 64 + row];
    float2 ml1 = g_ml[(128 + tile) * 64 + row];
    float M  = fmaxf(ml0.x, ml1.x);
    float w0 = __expf(ml0.x - M), w1 = __expf(ml1.x - M);
    float inv = 1.0f / (w0 * ml0.y + w1 * ml1.y);

    const float* P0 = g_part + ((size_t)tile * 64 + row) * 128;
    const float* P1 = g_part + ((size_t)(128 + tile) * 64 + row) * 128;
    float* og = out + ((size_t)b * SEQT + qt * 64 + row) * HDIM;
#pragma unroll
    for (int c = 0; c < 8; c += 4) {
        float4 a  = *reinterpret_cast<const float4*>(P0 + cg + c);
        float4 bb = *reinterpret_cast<const float4*>(P1 + cg + c);
        float4 r;
        r.x = (w0 * a.x + w1 * bb.x) * inv;
        r.y = (w0 * a.y + w1 * bb.y) * inv;
        r.z = (w0 * a.z + w1 * bb.z) * inv;
        r.w = (w0 * a.w + w1 * bb.w) * inv;
        *reinterpret_cast<float4*>(og + cg + c) = r;
    }
}

// ---------------------------------------------------------------------------
extern "C" void kernel_launch(void* const* d_in, const int* in_sizes, int n_in,
                              void* d_out, int out_size) {
    const float* x  = (const float*)d_in[0];
    const float* Wq = (const float*)d_in[1];
    const float* bq = (const float*)d_in[2];
    const float* Wk = (const float*)d_in[3];
    const float* bk = (const float*)d_in[4];
    const float* Wv = (const float*)d_in[5];
    const float* bv = (const float*)d_in[6];
    float* out = (float*)d_out;

    split_w_kernel<<<(3 * CDIM * HDIM) / 256, 256>>>(Wq, Wk, Wv);

    cudaFuncSetAttribute(fused_proj_kernel,
                         cudaFuncAttributeMaxDynamicSharedMemorySize, F_SMEM);
    fused_proj_kernel<<<dim3(BT / FM), 512, F_SMEM>>>(x, bq, bk, bv);

    cudaFuncSetAttribute(attn_kernel,
                         cudaFuncAttributeMaxDynamicSharedMemorySize, A_SMEM);
    attn_kernel<<<dim3(48 * BATCH), 256, A_SMEM>>>(out);

    reduce_kernel<<<512, 256>>>(out);
}

// round 14
// speedup vs baseline: 1.0583x; 1.0583x over previous
#include <cuda_runtime.h>
#include <cuda_bf16.h>

#define BATCH 8
#define SEQT 2048
#define CDIM 1024
#define HDIM 128
#define BT (BATCH * SEQT)   // 16384 tokens

// ---------------- device scratch (16B aligned) ----------------
__device__ __align__(16) __nv_bfloat16 g_whi[3][CDIM * HDIM];  // [c][h]
__device__ __align__(16) __nv_bfloat16 g_wlo[3][CDIM * HDIM];
__device__ __align__(16) __nv_bfloat16 g_Qhi[BT * HDIM];
__device__ __align__(16) __nv_bfloat16 g_Khi[BT * HDIM];
__device__ __align__(16) __nv_bfloat16 g_Vhi[BT * HDIM];
__device__ __align__(16) __nv_bfloat16 g_Vlo[BT * HDIM];
// split-K partials: [mode][tile=(qt-16)*8+b][row][dim]
__device__ __align__(16) float  g_part[2 * 128 * 64 * 128];   // 8 MB
__device__ __align__(16) float2 g_ml[2 * 128 * 64];

// slot tables: 48 slots (32 split halves + 16 unsplit), descending length
__device__ const unsigned char c_slot_qt[48] = {
    31,31,30,15,30,29,29,28,14,28,27,27,26,13,26,25,
    25,24,12,24,23,23,22,11,22,21,21,20,10,20,19,19,
    18, 9,18,17,17,16, 8,16, 7, 6, 5, 4, 3, 2, 1, 0};
__device__ const unsigned char c_slot_md[48] = {
    0,1,0,2,1,0,1,0,2,1,0,1,0,2,1,0,
    1,0,2,1,0,1,0,2,1,0,1,0,2,1,0,1,
    0,2,1,0,1,0,2,1,2,2,2,2,2,2,2,2};

// ---------------- helpers ----------------
__device__ __forceinline__ unsigned smem_u32(const void* p) {
    unsigned a;
    asm("{ .reg .u64 t; cvta.to.shared.u64 t, %1; cvt.u32.u64 %0, t; }"
        : "=r"(a) : "l"(p));
    return a;
}
__device__ __forceinline__ void ldsm4(unsigned* r, unsigned a) {
    asm volatile("ldmatrix.sync.aligned.m8n8.x4.shared.b16 {%0,%1,%2,%3}, [%4];"
                 : "=r"(r[0]), "=r"(r[1]), "=r"(r[2]), "=r"(r[3]) : "r"(a));
}
__device__ __forceinline__ void ldsm4t(unsigned* r, unsigned a) {
    asm volatile("ldmatrix.sync.aligned.m8n8.x4.trans.shared.b16 {%0,%1,%2,%3}, [%4];"
                 : "=r"(r[0]), "=r"(r[1]), "=r"(r[2]), "=r"(r[3]) : "r"(a));
}
__device__ __forceinline__ void mma16816(float* d, const unsigned* a, const unsigned* b) {
    asm volatile(
        "mma.sync.aligned.m16n8k16.row.col.f32.bf16.bf16.f32 "
        "{%0,%1,%2,%3}, {%4,%5,%6,%7}, {%8,%9}, {%0,%1,%2,%3};"
        : "+f"(d[0]), "+f"(d[1]), "+f"(d[2]), "+f"(d[3])
        : "r"(a[0]), "r"(a[1]), "r"(a[2]), "r"(a[3]), "r"(b[0]), "r"(b[1]));
}
__device__ __forceinline__ unsigned pack2(__nv_bfloat16 first, __nv_bfloat16 second) {
    return (unsigned)__bfloat16_as_ushort(first) |
           ((unsigned)__bfloat16_as_ushort(second) << 16);
}
__device__ __forceinline__ unsigned pack2f(float first, float second) {
    return pack2(__float2bfloat16(first), __float2bfloat16(second));
}
__device__ __forceinline__ void cp16(unsigned dst, const void* src) {
    asm volatile("cp.async.cg.shared.global [%0], [%1], 16;"
                 :: "r"(dst), "l"(src));
}
#define CP_COMMIT() asm volatile("cp.async.commit_group;")
#define CP_WAIT0()  asm volatile("cp.async.wait_group 0;" ::: "memory")
#define CP_WAIT1()  asm volatile("cp.async.wait_group 1;" ::: "memory")
#define BAR_PAIR(id) asm volatile("bar.sync %0, 64;" :: "r"(id) : "memory")

// ---------------- prep: split W fp32 -> bf16 hi/lo ----------------
__global__ __launch_bounds__(256) void split_w_kernel(
    const float* __restrict__ Wq, const float* __restrict__ Wk,
    const float* __restrict__ Wv) {
    int idx = blockIdx.x * 256 + threadIdx.x;
    int mat = idx >> 17;
    int r   = idx & 131071;
    const float* W = (mat == 0) ? Wq : (mat == 1) ? Wk : Wv;
    float v = W[r];
    __nv_bfloat16 hi = __float2bfloat16(v);
    g_whi[mat][r] = hi;
    g_wlo[mat][r] = __float2bfloat16(v - __bfloat162float(hi));
}

// ---------------- fused QKV projection (R12 version: FM=32, 2 CTAs/SM) ----
#define FM 32
#define FK 32
#define F_XF(s)    ((s) * 4096)
#define F_W(s, m)  (8192 + (s) * 32768 + (m) * 8192)
#define F_XH 73728
#define F_XL 76288
#define F_SMEM 78848
#define SWB(row, unit) (((row) << 8) + ((((unit) ^ ((row) & 7))) << 4))

__global__ __launch_bounds__(256, 2) void fused_proj_kernel(
    const float* __restrict__ x,
    const float* __restrict__ bq, const float* __restrict__ bk,
    const float* __restrict__ bv) {
    extern __shared__ char smc[];
    const unsigned sb = smem_u32(smc);
    const int tid = threadIdx.x;
    const int w   = tid >> 5;
    const int l   = tid & 31;
    const int wi  = w >> 2;
    const int wj  = w & 3;
    const int mi  = wi * 16;
    const int m0  = blockIdx.x * FM;

    const __nv_bfloat16* wsrc[4] = {g_whi[0], g_whi[1], g_whi[2], g_wlo[2]};
    const int xrow = tid >> 3, xq = tid & 7;

    auto issue_loads = [&](int ch, int s) {
        const int k0 = ch * FK;
        cp16(sb + F_XF(s) + xrow * 128 + xq * 16,
             x + (size_t)(m0 + xrow) * CDIM + k0 + xq * 4);
#pragma unroll
        for (int t = 0; t < 8; t++) {
            int u = tid + t * 256;
            int m = u >> 9;
            int r = (u >> 4) & 31;
            int q = u & 15;
            cp16(sb + F_W(s, m) + SWB(r, q),
                 wsrc[m] + (size_t)(k0 + r) * HDIM + q * 8);
        }
        CP_COMMIT();
    };

    float acc[3][4][4];
#pragma unroll
    for (int m = 0; m < 3; m++)
#pragma unroll
        for (int t = 0; t < 4; t++)
#pragma unroll
            for (int r = 0; r < 4; r++) acc[m][t][r] = 0.0f;

    issue_loads(0, 0);

    for (int ch = 0; ch < 32; ch++) {
        const int s = ch & 1;
        CP_WAIT0();
        __syncthreads();   // barA

        if (ch + 1 < 32) issue_loads(ch + 1, s ^ 1);

        {
            float4 v = *reinterpret_cast<const float4*>(
                smc + F_XF(s) + xrow * 128 + xq * 16);
            __nv_bfloat16 h0 = __float2bfloat16(v.x), h1 = __float2bfloat16(v.y);
            __nv_bfloat16 h2 = __float2bfloat16(v.z), h3 = __float2bfloat16(v.w);
            uint2 hv, lv;
            hv.x = pack2(h0, h1);
            hv.y = pack2(h2, h3);
            lv.x = pack2f(v.x - __bfloat162float(h0), v.y - __bfloat162float(h1));
            lv.y = pack2f(v.z - __bfloat162float(h2), v.w - __bfloat162float(h3));
            *reinterpret_cast<uint2*>(smc + F_XH + xrow * 80 + xq * 8) = hv;
            *reinterpret_cast<uint2*>(smc + F_XL + xrow * 80 + xq * 8) = lv;
        }
        __syncthreads();   // barB

#pragma unroll
        for (int ks = 0; ks < 2; ks++) {
            unsigned ah[4], al[4];
            unsigned a_off = (mi + (l & 15)) * 80 + (ks * 2 + (l >> 4)) * 16;
            ldsm4(ah, sb + F_XH + a_off);
            ldsm4(al, sb + F_XL + a_off);
            const int brow = ks * 16 + (l & 15);
#pragma unroll
            for (int m = 0; m < 3; m++) {
#pragma unroll
                for (int nt2 = 0; nt2 < 2; nt2++) {
                    unsigned bh[4];
                    unsigned unit = wj * 4 + nt2 * 2 + (l >> 4);
                    ldsm4t(bh, sb + F_W(s, m) + SWB(brow, unit));
                    mma16816(acc[m][2 * nt2],     ah, bh);
                    mma16816(acc[m][2 * nt2 + 1], ah, bh + 2);
                    mma16816(acc[m][2 * nt2],     al, bh);
                    mma16816(acc[m][2 * nt2 + 1], al, bh + 2);
                }
            }
#pragma unroll
            for (int nt2 = 0; nt2 < 2; nt2++) {
                unsigned bl[4];
                unsigned unit = wj * 4 + nt2 * 2 + (l >> 4);
                ldsm4t(bl, sb + F_W(s, 3) + SWB(brow, unit));
                mma16816(acc[2][2 * nt2],     ah, bl);
                mma16816(acc[2][2 * nt2 + 1], ah, bl + 2);
            }
        }
    }

    const int r0 = m0 + mi + (l >> 2);
    const int r1 = r0 + 8;
    const float* biases[3] = {bq, bk, bv};
#pragma unroll
    for (int m = 0; m < 3; m++) {
        __nv_bfloat16* ohi = (m == 0) ? g_Qhi : (m == 1) ? g_Khi : g_Vhi;
#pragma unroll
        for (int nt = 0; nt < 4; nt++) {
            int c = wj * 32 + nt * 8 + (l & 3) * 2;
            float b0 = biases[m][c], b1 = biases[m][c + 1];
            float vals[4] = {acc[m][nt][0] + b0, acc[m][nt][1] + b1,
                             acc[m][nt][2] + b0, acc[m][nt][3] + b1};
            int rows[4] = {r0, r0, r1, r1};
            int cols[4] = {c, c + 1, c, c + 1};
#pragma unroll
            for (int e = 0; e < 4; e++) {
                size_t off = (size_t)rows[e] * HDIM + cols[e];
                __nv_bfloat16 h = __float2bfloat16(vals[e]);
                ohi[off] = h;
                if (m == 2)   // only V keeps a lo tail (output path)
                    g_Vlo[off] = __float2bfloat16(vals[e] - __bfloat162float(h));
            }
        }
    }
}

// ---------------- flash attention: split-K, QK single-bf16 ----------------
#define S_QH 0
#define S_KH 16384
#define S_VH 32768
#define S_VL 49152
#define S_PH 65536
#define S_PL 73728
#define S_XB 81920
#define A_SMEM 82944
#define SWP(row, unit) (((row) << 7) + ((((unit) ^ ((row) & 7))) << 4))

__global__ __launch_bounds__(256, 2) void attn_kernel(float* __restrict__ out) {
    extern __shared__ char smc[];
    const unsigned sb = smem_u32(smc);
    const int tid = threadIdx.x;
    const int w   = tid >> 5;          // 0..7
    const int l   = tid & 31;
    const int wi  = w >> 1;            // m-block 0..3
    const int wj  = w & 1;             // n-half 0..1
    const int mi  = wi * 16;

    const int bid  = blockIdx.x;
    const int slot = bid >> 3;
    const int b    = bid & 7;
    const int qt   = c_slot_qt[slot];
    const int md   = c_slot_md[slot];  // 0=lower half, 1=upper half, 2=full
    const int h    = (qt + 2) >> 1;
    const int kb   = (md == 1) ? h : 0;
    const int ke   = (md == 0) ? (h - 1) : qt;
    const int q0   = qt * 64;
    const float scale = 0.03125f;      // 1024^-0.5

    const int lrow = (tid >> 4);
    const int lq   = tid & 15;

    // prologue: group0 = Q + K(kb); group1 = V(kb)
#pragma unroll
    for (int t = 0; t < 4; t++) {
        int row = lrow + t * 16;
        size_t gq = (size_t)(b * SEQT + q0 + row) * HDIM + lq * 8;
        size_t gk = (size_t)(b * SEQT + kb * 64 + row) * HDIM + lq * 8;
        cp16(sb + S_QH + SWB(row, lq), g_Qhi + gq);
        cp16(sb + S_KH + SWB(row, lq), g_Khi + gk);
    }
    CP_COMMIT();
#pragma unroll
    for (int t = 0; t < 4; t++) {
        int row = lrow + t * 16;
        size_t g = (size_t)(b * SEQT + kb * 64 + row) * HDIM + lq * 8;
        cp16(sb + S_VH + SWB(row, lq), g_Vhi + g);
        cp16(sb + S_VL + SWB(row, lq), g_Vlo + g);
    }
    CP_COMMIT();

    float m0_ = -1e30f, m1_ = -1e30f, l0_ = 0.0f, l1_ = 0.0f;
    float O[8][4];
#pragma unroll
    for (int t = 0; t < 8; t++)
#pragma unroll
        for (int r = 0; r < 4; r++) O[t][r] = 0.0f;

    const int row0 = mi + (l >> 2);
    const int row1 = row0 + 8;
    const int r0g  = q0 + row0;
    const int r1g  = r0g + 8;

    for (int kt = kb; kt <= ke; kt++) {
        const int k0 = kt * 64;
        CP_WAIT1();
        __syncthreads();   // (A) K visible

        float sacc[4][4];
#pragma unroll
        for (int t = 0; t < 4; t++)
#pragma unroll
            for (int r = 0; r < 4; r++) sacc[t][r] = 0.0f;

#pragma unroll
        for (int ks = 0; ks < 8; ks++) {
            unsigned ah[4];
            unsigned a_off = SWB(mi + (l & 15), ks * 2 + (l >> 4));
            ldsm4(ah, sb + S_QH + a_off);
#pragma unroll
            for (int nt2 = 0; nt2 < 2; nt2++) {
                unsigned bh[4];
                int brow = 32 * wj + nt2 * 16 + ((l >> 4) << 3) + (l & 7);
                unsigned b_off = SWB(brow, ks * 2 + ((l >> 3) & 1));
                ldsm4(bh, sb + S_KH + b_off);
                mma16816(sacc[2 * nt2],     ah, bh);
                mma16816(sacc[2 * nt2 + 1], ah, bh + 2);
            }
        }

        const bool mask_it = (kt == qt);
#pragma unroll
        for (int nt = 0; nt < 4; nt++) {
            int cg = k0 + 32 * wj + nt * 8 + (l & 3) * 2;
            float s0 = sacc[nt][0] * scale, s1 = sacc[nt][1] * scale;
            float s2 = sacc[nt][2] * scale, s3 = sacc[nt][3] * scale;
            if (mask_it) {
                if (cg     > r0g) s0 = -1e30f;
                if (cg + 1 > r0g) s1 = -1e30f;
                if (cg     > r1g) s2 = -1e30f;
                if (cg + 1 > r1g) s3 = -1e30f;
            }
            sacc[nt][0] = s0; sacc[nt][1] = s1; sacc[nt][2] = s2; sacc[nt][3] = s3;
        }
        float mt0 = -1e30f, mt1 = -1e30f;
#pragma unroll
        for (int nt = 0; nt < 4; nt++) {
            mt0 = fmaxf(mt0, fmaxf(sacc[nt][0], sacc[nt][1]));
            mt1 = fmaxf(mt1, fmaxf(sacc[nt][2], sacc[nt][3]));
        }
        mt0 = fmaxf(mt0, __shfl_xor_sync(0xffffffffu, mt0, 1));
        mt0 = fmaxf(mt0, __shfl_xor_sync(0xffffffffu, mt0, 2));
        mt1 = fmaxf(mt1, __shfl_xor_sync(0xffffffffu, mt1, 1));
        mt1 = fmaxf(mt1, __shfl_xor_sync(0xffffffffu, mt1, 2));

        float ls0 = 0.0f, ls1 = 0.0f;
#pragma unroll
        for (int nt = 0; nt < 4; nt++) {
            float p0 = __expf(sacc[nt][0] - mt0);
            float p1 = __expf(sacc[nt][1] - mt0);
            float p2 = __expf(sacc[nt][2] - mt1);
            float p3 = __expf(sacc[nt][3] - mt1);
            sacc[nt][0] = p0; sacc[nt][1] = p1; sacc[nt][2] = p2; sacc[nt][3] = p3;
            ls0 += p0 + p1; ls1 += p2 + p3;
        }
        ls0 += __shfl_xor_sync(0xffffffffu, ls0, 1);
        ls0 += __shfl_xor_sync(0xffffffffu, ls0, 2);
        ls1 += __shfl_xor_sync(0xffffffffu, ls1, 1);
        ls1 += __shfl_xor_sync(0xffffffffu, ls1, 2);

        // cross-warp softmax exchange: pair {2wi, 2wi+1} only (64 threads)
        if ((l & 3) == 0) {
            *reinterpret_cast<float2*>(smc + S_XB + row0 * 16 + 8 * wj) =
                make_float2(mt0, ls0);
            *reinterpret_cast<float2*>(smc + S_XB + row1 * 16 + 8 * wj) =
                make_float2(mt1, ls1);
        }
        BAR_PAIR(1 + wi);   // (B) partials visible within the pair

        float4 x0 = *reinterpret_cast<const float4*>(smc + S_XB + row0 * 16);
        float4 x1 = *reinterpret_cast<const float4*>(smc + S_XB + row1 * 16);

        float mn0 = fmaxf(m0_, fmaxf(x0.x, x0.z));
        float mn1 = fmaxf(m1_, fmaxf(x1.x, x1.z));
        float al0 = __expf(m0_ - mn0), al1 = __expf(m1_ - mn1);
        float f00 = __expf(x0.x - mn0), f01 = __expf(x0.z - mn0);
        float f10 = __expf(x1.x - mn1), f11 = __expf(x1.z - mn1);
        l0_ = l0_ * al0 + x0.y * f00 + x0.w * f01;
        l1_ = l1_ * al1 + x1.y * f10 + x1.w * f11;
        m0_ = mn0; m1_ = mn1;
        float fme0 = wj ? f01 : f00;
        float fme1 = wj ? f11 : f10;

#pragma unroll
        for (int t = 0; t < 8; t++) {
            O[t][0] *= al0; O[t][1] *= al0; O[t][2] *= al1; O[t][3] *= al1;
        }

        CP_WAIT0();        // V(kt) landed

#pragma unroll
        for (int nt = 0; nt < 4; nt++) {
            float p00 = sacc[nt][0] * fme0, p01 = sacc[nt][1] * fme0;
            float p10 = sacc[nt][2] * fme1, p11 = sacc[nt][3] * fme1;
            __nv_bfloat16 h00 = __float2bfloat16(p00), h01 = __float2bfloat16(p01);
            __nv_bfloat16 h10 = __float2bfloat16(p10), h11 = __float2bfloat16(p11);
            int unit = 4 * wj + nt;
            unsigned o0 = SWP(row0, unit) + (l & 3) * 4;
            unsigned o1 = SWP(row1, unit) + (l & 3) * 4;
            *reinterpret_cast<unsigned*>(smc + S_PH + o0) = pack2(h00, h01);
            *reinterpret_cast<unsigned*>(smc + S_PH + o1) = pack2(h10, h11);
            *reinterpret_cast<unsigned*>(smc + S_PL + o0) =
                pack2f(p00 - __bfloat162float(h00), p01 - __bfloat162float(h01));
            *reinterpret_cast<unsigned*>(smc + S_PL + o1) =
                pack2f(p10 - __bfloat162float(h10), p11 - __bfloat162float(h11));
        }
        __syncthreads();   // (C) P + V visible; K/xbuf reads all done

        if (kt < ke) {
            const int kn = k0 + 64;
#pragma unroll
            for (int t = 0; t < 4; t++) {
                int row = lrow + t * 16;
                size_t g = (size_t)(b * SEQT + kn + row) * HDIM + lq * 8;
                cp16(sb + S_KH + SWB(row, lq), g_Khi + g);
            }
            CP_COMMIT();
        }

#pragma unroll
        for (int ks2 = 0; ks2 < 4; ks2++) {
            unsigned ph[4], pl2[4];
            unsigned p_off = SWP(mi + (l & 15), ks2 * 2 + (l >> 4));
            ldsm4(ph,  sb + S_PH + p_off);
            ldsm4(pl2, sb + S_PL + p_off);
#pragma unroll
            for (int dt2 = 0; dt2 < 4; dt2++) {
                unsigned vh[4], vl[4];
                int vrow = ks2 * 16 + (l & 15);
                unsigned v_off = SWB(vrow, 8 * wj + dt2 * 2 + (l >> 4));
                ldsm4t(vh, sb + S_VH + v_off);
                ldsm4t(vl, sb + S_VL + v_off);
                mma16816(O[2 * dt2],     ph,  vh);
                mma16816(O[2 * dt2 + 1], ph,  vh + 2);
                mma16816(O[2 * dt2],     ph,  vl);
                mma16816(O[2 * dt2 + 1], ph,  vl + 2);
                mma16816(O[2 * dt2],     pl2, vh);
                mma16816(O[2 * dt2 + 1], pl2, vh + 2);
            }
        }
        __syncthreads();   // (D) PV reads done

        if (kt < ke) {
            const int kn = k0 + 64;
#pragma unroll
            for (int t = 0; t < 4; t++) {
                int row = lrow + t * 16;
                size_t g = (size_t)(b * SEQT + kn + row) * HDIM + lq * 8;
                cp16(sb + S_VH + SWB(row, lq), g_Vhi + g);
                cp16(sb + S_VL + SWB(row, lq), g_Vlo + g);
            }
            CP_COMMIT();
        }
    }

    if (md == 2) {
        float inv0 = 1.0f / l0_, inv1 = 1.0f / l1_;
#pragma unroll
        for (int dt = 0; dt < 8; dt++) {
            int c = 64 * wj + dt * 8 + (l & 3) * 2;
            float2 v0 = make_float2(O[dt][0] * inv0, O[dt][1] * inv0);
            float2 v1 = make_float2(O[dt][2] * inv1, O[dt][3] * inv1);
            *reinterpret_cast<float2*>(out + ((size_t)b * SEQT + r0g) * HDIM + c) = v0;
            *reinterpret_cast<float2*>(out + ((size_t)b * SEQT + r1g) * HDIM + c) = v1;
        }
    } else {
        const int tile = (qt - 16) * 8 + b;
        float* P = g_part + ((size_t)(md * 128 + tile) * 64) * 128;
#pragma unroll
        for (int dt = 0; dt < 8; dt++) {
            int c = 64 * wj + dt * 8 + (l & 3) * 2;
            *reinterpret_cast<float2*>(P + (size_t)row0 * 128 + c) =
                make_float2(O[dt][0], O[dt][1]);
            *reinterpret_cast<float2*>(P + (size_t)row1 * 128 + c) =
                make_float2(O[dt][2], O[dt][3]);
        }
        if (wj == 0 && (l & 3) == 0) {
            g_ml[(md * 128 + tile) * 64 + row0] = make_float2(m0_, l0_);
            g_ml[(md * 128 + tile) * 64 + row1] = make_float2(m1_, l1_);
        }
    }
}

// ---------------- split-K reduce (512 CTAs, 16 rows each) -------------------
__global__ __launch_bounds__(256) void reduce_kernel(float* __restrict__ out) {
    const int bid  = blockIdx.x;            // 0..511
    const int tile = bid >> 2;              // 0..127
    const int quad = bid & 3;
    const int qt = 16 + (tile >> 3);
    const int b  = tile & 7;
    const int row = quad * 16 + (threadIdx.x >> 4);   // 0..63
    const int cg  = (threadIdx.x & 15) * 8;

    float2 ml0 = g_ml[tile * 64 + row];
    float2 ml1 = g_ml[(128 + tile) * 64 + row];
    float M  = fmaxf(ml0.x, ml1.x);
    float w0 = __expf(ml0.x - M), w1 = __expf(ml1.x - M);
    float inv = 1.0f / (w0 * ml0.y + w1 * ml1.y);

    const float* P0 = g_part + ((size_t)tile * 64 + row) * 128;
    const float* P1 = g_part + ((size_t)(128 + tile) * 64 + row) * 128;
    float* og = out + ((size_t)b * SEQT + qt * 64 + row) * HDIM;
#pragma unroll
    for (int c = 0; c < 8; c += 4) {
        float4 a  = *reinterpret_cast<const float4*>(P0 + cg + c);
        float4 bb = *reinterpret_cast<const float4*>(P1 + cg + c);
        float4 r;
        r.x = (w0 * a.x + w1 * bb.x) * inv;
        r.y = (w0 * a.y + w1 * bb.y) * inv;
        r.z = (w0 * a.z + w1 * bb.z) * inv;
        r.w = (w0 * a.w + w1 * bb.w) * inv;
        *reinterpret_cast<float4*>(og + cg + c) = r;
    }
}

// ---------------------------------------------------------------------------
extern "C" void kernel_launch(void* const* d_in, const int* in_sizes, int n_in,
                              void* d_out, int out_size) {
    const float* x  = (const float*)d_in[0];
    const float* Wq = (const float*)d_in[1];
    const float* bq = (const float*)d_in[2];
    const float* Wk = (const float*)d_in[3];
    const float* bk = (const float*)d_in[4];
    const float* Wv = (const float*)d_in[5];
    const float* bv = (const float*)d_in[6];
    float* out = (float*)d_out;

    split_w_kernel<<<(3 * CDIM * HDIM) / 256, 256>>>(Wq, Wk, Wv);

    cudaFuncSetAttribute(fused_proj_kernel,
                         cudaFuncAttributeMaxDynamicSharedMemorySize, F_SMEM);
    fused_proj_kernel<<<dim3(BT / FM), 256, F_SMEM>>>(x, bq, bk, bv);

    cudaFuncSetAttribute(attn_kernel,
                         cudaFuncAttributeMaxDynamicSharedMemorySize, A_SMEM);
    attn_kernel<<<dim3(48 * BATCH), 256, A_SMEM>>>(out);

    reduce_kernel<<<512, 256>>>(out);
}

// round 15
// speedup vs baseline: 1.1162x; 1.0548x over previous
#include <cuda_runtime.h>
#include <cuda_bf16.h>

#define BATCH 8
#define SEQT 2048
#define CDIM 1024
#define HDIM 128
#define BT (BATCH * SEQT)   // 16384 tokens

// ---------------- device scratch (16B aligned) ----------------
__device__ __align__(16) __nv_bfloat16 g_whi[3][CDIM * HDIM];  // [c][h]
__device__ __align__(16) __nv_bfloat16 g_wlo[3][CDIM * HDIM];
__device__ __align__(16) __nv_bfloat16 g_Qhi[BT * HDIM];
__device__ __align__(16) __nv_bfloat16 g_Khi[BT * HDIM];
__device__ __align__(16) __nv_bfloat16 g_Vhi[BT * HDIM];
__device__ __align__(16) __nv_bfloat16 g_Vlo[BT * HDIM];
// split-K partials: [mode][tile=(qt-16)*8+b][row][dim]
__device__ __align__(16) float  g_part[2 * 128 * 64 * 128];   // 8 MB
__device__ __align__(16) float2 g_ml[2 * 128 * 64];

// slot tables: 48 slots (32 split halves + 16 unsplit), descending length
__device__ const unsigned char c_slot_qt[48] = {
    31,31,30,15,30,29,29,28,14,28,27,27,26,13,26,25,
    25,24,12,24,23,23,22,11,22,21,21,20,10,20,19,19,
    18, 9,18,17,17,16, 8,16, 7, 6, 5, 4, 3, 2, 1, 0};
__device__ const unsigned char c_slot_md[48] = {
    0,1,0,2,1,0,1,0,2,1,0,1,0,2,1,0,
    1,0,2,1,0,1,0,2,1,0,1,0,2,1,0,1,
    0,2,1,0,1,0,2,1,2,2,2,2,2,2,2,2};

// ---------------- helpers ----------------
__device__ __forceinline__ unsigned smem_u32(const void* p) {
    unsigned a;
    asm("{ .reg .u64 t; cvta.to.shared.u64 t, %1; cvt.u32.u64 %0, t; }"
        : "=r"(a) : "l"(p));
    return a;
}
__device__ __forceinline__ void ldsm4(unsigned* r, unsigned a) {
    asm volatile("ldmatrix.sync.aligned.m8n8.x4.shared.b16 {%0,%1,%2,%3}, [%4];"
                 : "=r"(r[0]), "=r"(r[1]), "=r"(r[2]), "=r"(r[3]) : "r"(a));
}
__device__ __forceinline__ void ldsm4t(unsigned* r, unsigned a) {
    asm volatile("ldmatrix.sync.aligned.m8n8.x4.trans.shared.b16 {%0,%1,%2,%3}, [%4];"
                 : "=r"(r[0]), "=r"(r[1]), "=r"(r[2]), "=r"(r[3]) : "r"(a));
}
__device__ __forceinline__ void mma16816(float* d, const unsigned* a, const unsigned* b) {
    asm volatile(
        "mma.sync.aligned.m16n8k16.row.col.f32.bf16.bf16.f32 "
        "{%0,%1,%2,%3}, {%4,%5,%6,%7}, {%8,%9}, {%0,%1,%2,%3};"
        : "+f"(d[0]), "+f"(d[1]), "+f"(d[2]), "+f"(d[3])
        : "r"(a[0]), "r"(a[1]), "r"(a[2]), "r"(a[3]), "r"(b[0]), "r"(b[1]));
}
__device__ __forceinline__ unsigned pack2(__nv_bfloat16 first, __nv_bfloat16 second) {
    return (unsigned)__bfloat16_as_ushort(first) |
           ((unsigned)__bfloat16_as_ushort(second) << 16);
}
__device__ __forceinline__ unsigned pack2f(float first, float second) {
    return pack2(__float2bfloat16(first), __float2bfloat16(second));
}
__device__ __forceinline__ void cp16(unsigned dst, const void* src) {
    asm volatile("cp.async.cg.shared.global [%0], [%1], 16;"
                 :: "r"(dst), "l"(src));
}
#define CP_COMMIT() asm volatile("cp.async.commit_group;")
#define CP_WAIT0()  asm volatile("cp.async.wait_group 0;" ::: "memory")
#define CP_WAIT1()  asm volatile("cp.async.wait_group 1;" ::: "memory")
#define BAR_PAIR(id) asm volatile("bar.sync %0, 64;" :: "r"(id) : "memory")
// 256B-row swizzle (128 bf16) and 128B-row swizzle (64 bf16)
#define SWB(row, unit) (((row) << 8) + ((((unit) ^ ((row) & 7))) << 4))
#define SWP(row, unit) (((row) << 7) + ((((unit) ^ ((row) & 7))) << 4))

// ---------------- prep: split W fp32 -> bf16 hi/lo ----------------
__global__ __launch_bounds__(256) void split_w_kernel(
    const float* __restrict__ Wq, const float* __restrict__ Wk,
    const float* __restrict__ Wv) {
    int idx = blockIdx.x * 256 + threadIdx.x;
    int mat = idx >> 17;
    int r   = idx & 131071;
    const float* W = (mat == 0) ? Wq : (mat == 1) ? Wk : Wv;
    float v = W[r];
    __nv_bfloat16 hi = __float2bfloat16(v);
    g_whi[mat][r] = hi;
    g_wlo[mat][r] = __float2bfloat16(v - __bfloat162float(hi));
}

// ---------------- fused QKV projection: FM=64 x FN=64 N-split -------------
// grid 512 = 256 token-tiles x 2 N-halves; 256 thr (8 warps = 4m x 2n);
// 2 CTAs/SM retained; W L2 traffic halved vs R12.
#define FM 64
#define FK 32
#define F_STG 24576                       // stage: x 8KB + 4 W tiles 16KB
#define F_XF(s)    ((s) * F_STG)
#define F_W(s, m)  ((s) * F_STG + 8192 + (m) * 4096)
#define F_XH 49152                        // 64 rows stride 80B
#define F_XL 54272
#define F_SMEM 59392

__global__ __launch_bounds__(256, 2) void fused_proj_kernel(
    const float* __restrict__ x,
    const float* __restrict__ bq, const float* __restrict__ bk,
    const float* __restrict__ bv) {
    extern __shared__ char smc[];
    const unsigned sb = smem_u32(smc);
    const int tid = threadIdx.x;
    const int w   = tid >> 5;
    const int l   = tid & 31;
    const int wi  = w >> 1;            // m-block 0..3 (16 rows)
    const int wj  = w & 1;             // n-quarter 0..1 (32 cols of this half)
    const int mi  = wi * 16;
    const int tile = blockIdx.x >> 1;  // 0..255
    const int nh   = blockIdx.x & 1;   // N-half
    const int m0 = tile * FM;
    const int n0 = nh * 64;

    const __nv_bfloat16* wsrc[4] = {g_whi[0] + n0, g_whi[1] + n0,
                                    g_whi[2] + n0, g_wlo[2] + n0};

    auto issue_loads = [&](int ch, int s) {
        const int k0 = ch * FK;
        // x fp32: 64 rows x 32 fp32 (128B rows), 2 cp16/thread
#pragma unroll
        for (int t = 0; t < 2; t++) {
            int u = tid + t * 256;
            int row = u >> 3, q = u & 7;
            cp16(sb + F_XF(s) + row * 128 + q * 16,
                 x + (size_t)(m0 + row) * CDIM + k0 + q * 4);
        }
        // W: 4 tensors x 32 rows x 64 bf16 (128B rows), 4 cp16/thread
#pragma unroll
        for (int t = 0; t < 4; t++) {
            int u = tid + t * 256;           // 0..1023
            int m = u >> 8;
            int r = (u >> 3) & 31;
            int q = u & 7;
            cp16(sb + F_W(s, m) + SWP(r, q),
                 wsrc[m] + (size_t)(k0 + r) * HDIM + q * 8);
        }
        CP_COMMIT();
    };

    float acc[3][4][4];
#pragma unroll
    for (int m = 0; m < 3; m++)
#pragma unroll
        for (int t = 0; t < 4; t++)
#pragma unroll
            for (int r = 0; r < 4; r++) acc[m][t][r] = 0.0f;

    issue_loads(0, 0);

    for (int ch = 0; ch < 32; ch++) {
        const int s = ch & 1;
        CP_WAIT0();
        __syncthreads();   // barA: stage s landed

        if (ch + 1 < 32) issue_loads(ch + 1, s ^ 1);

        // convert x fp32 -> bf16 hi/lo (2 float4/thread covers 64x32)
#pragma unroll
        for (int t = 0; t < 2; t++) {
            int u = tid + t * 256;
            int row = u >> 3, q = u & 7;
            float4 v = *reinterpret_cast<const float4*>(
                smc + F_XF(s) + row * 128 + q * 16);
            __nv_bfloat16 h0 = __float2bfloat16(v.x), h1 = __float2bfloat16(v.y);
            __nv_bfloat16 h2 = __float2bfloat16(v.z), h3 = __float2bfloat16(v.w);
            uint2 hv, lv;
            hv.x = pack2(h0, h1);
            hv.y = pack2(h2, h3);
            lv.x = pack2f(v.x - __bfloat162float(h0), v.y - __bfloat162float(h1));
            lv.y = pack2f(v.z - __bfloat162float(h2), v.w - __bfloat162float(h3));
            *reinterpret_cast<uint2*>(smc + F_XH + row * 80 + q * 8) = hv;
            *reinterpret_cast<uint2*>(smc + F_XL + row * 80 + q * 8) = lv;
        }
        __syncthreads();   // barB: conversion visible

#pragma unroll
        for (int ks = 0; ks < 2; ks++) {
            unsigned ah[4], al[4];
            unsigned a_off = (mi + (l & 15)) * 80 + (ks * 2 + (l >> 4)) * 16;
            ldsm4(ah, sb + F_XH + a_off);
            ldsm4(al, sb + F_XL + a_off);
            const int brow = ks * 16 + (l & 15);
#pragma unroll
            for (int m = 0; m < 3; m++) {
#pragma unroll
                for (int nt2 = 0; nt2 < 2; nt2++) {
                    unsigned bh[4];
                    unsigned unit = wj * 4 + nt2 * 2 + (l >> 4);
                    ldsm4t(bh, sb + F_W(s, m) + SWP(brow, unit));
                    mma16816(acc[m][2 * nt2],     ah, bh);
                    mma16816(acc[m][2 * nt2 + 1], ah, bh + 2);
                    mma16816(acc[m][2 * nt2],     al, bh);
                    mma16816(acc[m][2 * nt2 + 1], al, bh + 2);
                }
            }
#pragma unroll
            for (int nt2 = 0; nt2 < 2; nt2++) {
                unsigned bl[4];
                unsigned unit = wj * 4 + nt2 * 2 + (l >> 4);
                ldsm4t(bl, sb + F_W(s, 3) + SWP(brow, unit));
                mma16816(acc[2][2 * nt2],     ah, bl);
                mma16816(acc[2][2 * nt2 + 1], ah, bl + 2);
            }
        }
    }

    const int r0 = m0 + mi + (l >> 2);
    const int r1 = r0 + 8;
    const float* biases[3] = {bq, bk, bv};
#pragma unroll
    for (int m = 0; m < 3; m++) {
        __nv_bfloat16* ohi = (m == 0) ? g_Qhi : (m == 1) ? g_Khi : g_Vhi;
#pragma unroll
        for (int nt = 0; nt < 4; nt++) {
            int c = n0 + wj * 32 + nt * 8 + (l & 3) * 2;
            float b0 = biases[m][c], b1 = biases[m][c + 1];
            float vals[4] = {acc[m][nt][0] + b0, acc[m][nt][1] + b1,
                             acc[m][nt][2] + b0, acc[m][nt][3] + b1};
            int rows[4] = {r0, r0, r1, r1};
            int cols[4] = {c, c + 1, c, c + 1};
#pragma unroll
            for (int e = 0; e < 4; e++) {
                size_t off = (size_t)rows[e] * HDIM + cols[e];
                __nv_bfloat16 h = __float2bfloat16(vals[e]);
                ohi[off] = h;
                if (m == 2)   // only V keeps a lo tail (output path)
                    g_Vlo[off] = __float2bfloat16(vals[e] - __bfloat162float(h));
            }
        }
    }
}

// ---------------- flash attention: split-K, QK single-bf16 ----------------
#define S_QH 0
#define S_KH 16384
#define S_VH 32768
#define S_VL 49152
#define S_PH 65536
#define S_PL 73728
#define S_XB 81920
#define A_SMEM 82944

__global__ __launch_bounds__(256, 2) void attn_kernel(float* __restrict__ out) {
    extern __shared__ char smc[];
    const unsigned sb = smem_u32(smc);
    const int tid = threadIdx.x;
    const int w   = tid >> 5;          // 0..7
    const int l   = tid & 31;
    const int wi  = w >> 1;            // m-block 0..3
    const int wj  = w & 1;             // n-half 0..1
    const int mi  = wi * 16;

    const int bid  = blockIdx.x;
    const int slot = bid >> 3;
    const int b    = bid & 7;
    const int qt   = c_slot_qt[slot];
    const int md   = c_slot_md[slot];  // 0=lower half, 1=upper half, 2=full
    const int h    = (qt + 2) >> 1;
    const int kb   = (md == 1) ? h : 0;
    const int ke   = (md == 0) ? (h - 1) : qt;
    const int q0   = qt * 64;
    const float scale = 0.03125f;      // 1024^-0.5

    const int lrow = (tid >> 4);
    const int lq   = tid & 15;

    // prologue: group0 = Q + K(kb); group1 = V(kb)
#pragma unroll
    for (int t = 0; t < 4; t++) {
        int row = lrow + t * 16;
        size_t gq = (size_t)(b * SEQT + q0 + row) * HDIM + lq * 8;
        size_t gk = (size_t)(b * SEQT + kb * 64 + row) * HDIM + lq * 8;
        cp16(sb + S_QH + SWB(row, lq), g_Qhi + gq);
        cp16(sb + S_KH + SWB(row, lq), g_Khi + gk);
    }
    CP_COMMIT();
#pragma unroll
    for (int t = 0; t < 4; t++) {
        int row = lrow + t * 16;
        size_t g = (size_t)(b * SEQT + kb * 64 + row) * HDIM + lq * 8;
        cp16(sb + S_VH + SWB(row, lq), g_Vhi + g);
        cp16(sb + S_VL + SWB(row, lq), g_Vlo + g);
    }
    CP_COMMIT();

    float m0_ = -1e30f, m1_ = -1e30f, l0_ = 0.0f, l1_ = 0.0f;
    float O[8][4];
#pragma unroll
    for (int t = 0; t < 8; t++)
#pragma unroll
        for (int r = 0; r < 4; r++) O[t][r] = 0.0f;

    const int row0 = mi + (l >> 2);
    const int row1 = row0 + 8;
    const int r0g  = q0 + row0;
    const int r1g  = r0g + 8;

    for (int kt = kb; kt <= ke; kt++) {
        const int k0 = kt * 64;
        CP_WAIT1();
        __syncthreads();   // (A) K visible

        float sacc[4][4];
#pragma unroll
        for (int t = 0; t < 4; t++)
#pragma unroll
            for (int r = 0; r < 4; r++) sacc[t][r] = 0.0f;

#pragma unroll
        for (int ks = 0; ks < 8; ks++) {
            unsigned ah[4];
            unsigned a_off = SWB(mi + (l & 15), ks * 2 + (l >> 4));
            ldsm4(ah, sb + S_QH + a_off);
#pragma unroll
            for (int nt2 = 0; nt2 < 2; nt2++) {
                unsigned bh[4];
                int brow = 32 * wj + nt2 * 16 + ((l >> 4) << 3) + (l & 7);
                unsigned b_off = SWB(brow, ks * 2 + ((l >> 3) & 1));
                ldsm4(bh, sb + S_KH + b_off);
                mma16816(sacc[2 * nt2],     ah, bh);
                mma16816(sacc[2 * nt2 + 1], ah, bh + 2);
            }
        }

        const bool mask_it = (kt == qt);
#pragma unroll
        for (int nt = 0; nt < 4; nt++) {
            int cg = k0 + 32 * wj + nt * 8 + (l & 3) * 2;
            float s0 = sacc[nt][0] * scale, s1 = sacc[nt][1] * scale;
            float s2 = sacc[nt][2] * scale, s3 = sacc[nt][3] * scale;
            if (mask_it) {
                if (cg     > r0g) s0 = -1e30f;
                if (cg + 1 > r0g) s1 = -1e30f;
                if (cg     > r1g) s2 = -1e30f;
                if (cg + 1 > r1g) s3 = -1e30f;
            }
            sacc[nt][0] = s0; sacc[nt][1] = s1; sacc[nt][2] = s2; sacc[nt][3] = s3;
        }
        float mt0 = -1e30f, mt1 = -1e30f;
#pragma unroll
        for (int nt = 0; nt < 4; nt++) {
            mt0 = fmaxf(mt0, fmaxf(sacc[nt][0], sacc[nt][1]));
            mt1 = fmaxf(mt1, fmaxf(sacc[nt][2], sacc[nt][3]));
        }
        mt0 = fmaxf(mt0, __shfl_xor_sync(0xffffffffu, mt0, 1));
        mt0 = fmaxf(mt0, __shfl_xor_sync(0xffffffffu, mt0, 2));
        mt1 = fmaxf(mt1, __shfl_xor_sync(0xffffffffu, mt1, 1));
        mt1 = fmaxf(mt1, __shfl_xor_sync(0xffffffffu, mt1, 2));

        float ls0 = 0.0f, ls1 = 0.0f;
#pragma unroll
        for (int nt = 0; nt < 4; nt++) {
            float p0 = __expf(sacc[nt][0] - mt0);
            float p1 = __expf(sacc[nt][1] - mt0);
            float p2 = __expf(sacc[nt][2] - mt1);
            float p3 = __expf(sacc[nt][3] - mt1);
            sacc[nt][0] = p0; sacc[nt][1] = p1; sacc[nt][2] = p2; sacc[nt][3] = p3;
            ls0 += p0 + p1; ls1 += p2 + p3;
        }
        ls0 += __shfl_xor_sync(0xffffffffu, ls0, 1);
        ls0 += __shfl_xor_sync(0xffffffffu, ls0, 2);
        ls1 += __shfl_xor_sync(0xffffffffu, ls1, 1);
        ls1 += __shfl_xor_sync(0xffffffffu, ls1, 2);

        // cross-warp softmax exchange: pair {2wi, 2wi+1} only (64 threads)
        if ((l & 3) == 0) {
            *reinterpret_cast<float2*>(smc + S_XB + row0 * 16 + 8 * wj) =
                make_float2(mt0, ls0);
            *reinterpret_cast<float2*>(smc + S_XB + row1 * 16 + 8 * wj) =
                make_float2(mt1, ls1);
        }
        BAR_PAIR(1 + wi);   // (B) partials visible within the pair

        float4 x0 = *reinterpret_cast<const float4*>(smc + S_XB + row0 * 16);
        float4 x1 = *reinterpret_cast<const float4*>(smc + S_XB + row1 * 16);

        float mn0 = fmaxf(m0_, fmaxf(x0.x, x0.z));
        float mn1 = fmaxf(m1_, fmaxf(x1.x, x1.z));
        float al0 = __expf(m0_ - mn0), al1 = __expf(m1_ - mn1);
        float f00 = __expf(x0.x - mn0), f01 = __expf(x0.z - mn0);
        float f10 = __expf(x1.x - mn1), f11 = __expf(x1.z - mn1);
        l0_ = l0_ * al0 + x0.y * f00 + x0.w * f01;
        l1_ = l1_ * al1 + x1.y * f10 + x1.w * f11;
        m0_ = mn0; m1_ = mn1;
        float fme0 = wj ? f01 : f00;
        float fme1 = wj ? f11 : f10;

#pragma unroll
        for (int t = 0; t < 8; t++) {
            O[t][0] *= al0; O[t][1] *= al0; O[t][2] *= al1; O[t][3] *= al1;
        }

        CP_WAIT0();        // V(kt) landed

#pragma unroll
        for (int nt = 0; nt < 4; nt++) {
            float p00 = sacc[nt][0] * fme0, p01 = sacc[nt][1] * fme0;
            float p10 = sacc[nt][2] * fme1, p11 = sacc[nt][3] * fme1;
            __nv_bfloat16 h00 = __float2bfloat16(p00), h01 = __float2bfloat16(p01);
            __nv_bfloat16 h10 = __float2bfloat16(p10), h11 = __float2bfloat16(p11);
            int unit = 4 * wj + nt;
            unsigned o0 = SWP(row0, unit) + (l & 3) * 4;
            unsigned o1 = SWP(row1, unit) + (l & 3) * 4;
            *reinterpret_cast<unsigned*>(smc + S_PH + o0) = pack2(h00, h01);
            *reinterpret_cast<unsigned*>(smc + S_PH + o1) = pack2(h10, h11);
            *reinterpret_cast<unsigned*>(smc + S_PL + o0) =
                pack2f(p00 - __bfloat162float(h00), p01 - __bfloat162float(h01));
            *reinterpret_cast<unsigned*>(smc + S_PL + o1) =
                pack2f(p10 - __bfloat162float(h10), p11 - __bfloat162float(h11));
        }
        __syncthreads();   // (C) P + V visible; K/xbuf reads all done

        if (kt < ke) {
            const int kn = k0 + 64;
#pragma unroll
            for (int t = 0; t < 4; t++) {
                int row = lrow + t * 16;
                size_t g = (size_t)(b * SEQT + kn + row) * HDIM + lq * 8;
                cp16(sb + S_KH + SWB(row, lq), g_Khi + g);
            }
            CP_COMMIT();
        }

#pragma unroll
        for (int ks2 = 0; ks2 < 4; ks2++) {
            unsigned ph[4], pl2[4];
            unsigned p_off = SWP(mi + (l & 15), ks2 * 2 + (l >> 4));
            ldsm4(ph,  sb + S_PH + p_off);
            ldsm4(pl2, sb + S_PL + p_off);
#pragma unroll
            for (int dt2 = 0; dt2 < 4; dt2++) {
                unsigned vh[4], vl[4];
                int vrow = ks2 * 16 + (l & 15);
                unsigned v_off = SWB(vrow, 8 * wj + dt2 * 2 + (l >> 4));
                ldsm4t(vh, sb + S_VH + v_off);
                ldsm4t(vl, sb + S_VL + v_off);
                mma16816(O[2 * dt2],     ph,  vh);
                mma16816(O[2 * dt2 + 1], ph,  vh + 2);
                mma16816(O[2 * dt2],     ph,  vl);
                mma16816(O[2 * dt2 + 1], ph,  vl + 2);
                mma16816(O[2 * dt2],     pl2, vh);
                mma16816(O[2 * dt2 + 1], pl2, vh + 2);
            }
        }
        __syncthreads();   // (D) PV reads done

        if (kt < ke) {
            const int kn = k0 + 64;
#pragma unroll
            for (int t = 0; t < 4; t++) {
                int row = lrow + t * 16;
                size_t g = (size_t)(b * SEQT + kn + row) * HDIM + lq * 8;
                cp16(sb + S_VH + SWB(row, lq), g_Vhi + g);
                cp16(sb + S_VL + SWB(row, lq), g_Vlo + g);
            }
            CP_COMMIT();
        }
    }

    if (md == 2) {
        float inv0 = 1.0f / l0_, inv1 = 1.0f / l1_;
#pragma unroll
        for (int dt = 0; dt < 8; dt++) {
            int c = 64 * wj + dt * 8 + (l & 3) * 2;
            float2 v0 = make_float2(O[dt][0] * inv0, O[dt][1] * inv0);
            float2 v1 = make_float2(O[dt][2] * inv1, O[dt][3] * inv1);
            *reinterpret_cast<float2*>(out + ((size_t)b * SEQT + r0g) * HDIM + c) = v0;
            *reinterpret_cast<float2*>(out + ((size_t)b * SEQT + r1g) * HDIM + c) = v1;
        }
    } else {
        const int tile = (qt - 16) * 8 + b;
        float* P = g_part + ((size_t)(md * 128 + tile) * 64) * 128;
#pragma unroll
        for (int dt = 0; dt < 8; dt++) {
            int c = 64 * wj + dt * 8 + (l & 3) * 2;
            *reinterpret_cast<float2*>(P + (size_t)row0 * 128 + c) =
                make_float2(O[dt][0], O[dt][1]);
            *reinterpret_cast<float2*>(P + (size_t)row1 * 128 + c) =
                make_float2(O[dt][2], O[dt][3]);
        }
        if (wj == 0 && (l & 3) == 0) {
            g_ml[(md * 128 + tile) * 64 + row0] = make_float2(m0_, l0_);
            g_ml[(md * 128 + tile) * 64 + row1] = make_float2(m1_, l1_);
        }
    }
}

// ---------------- split-K reduce (512 CTAs, 16 rows each) -------------------
__global__ __launch_bounds__(256) void reduce_kernel(float* __restrict__ out) {
    const int bid  = blockIdx.x;            // 0..511
    const int tile = bid >> 2;              // 0..127
    const int quad = bid & 3;
    const int qt = 16 + (tile >> 3);
    const int b  = tile & 7;
    const int row = quad * 16 + (threadIdx.x >> 4);   // 0..63
    const int cg  = (threadIdx.x & 15) * 8;

    float2 ml0 = g_ml[tile * 64 + row];
    float2 ml1 = g_ml[(128 + tile) * 64 + row];
    float M  = fmaxf(ml0.x, ml1.x);
    float w0 = __expf(ml0.x - M), w1 = __expf(ml1.x - M);
    float inv = 1.0f / (w0 * ml0.y + w1 * ml1.y);

    const float* P0 = g_part + ((size_t)tile * 64 + row) * 128;
    const float* P1 = g_part + ((size_t)(128 + tile) * 64 + row) * 128;
    float* og = out + ((size_t)b * SEQT + qt * 64 + row) * HDIM;
#pragma unroll
    for (int c = 0; c < 8; c += 4) {
        float4 a  = *reinterpret_cast<const float4*>(P0 + cg + c);
        float4 bb = *reinterpret_cast<const float4*>(P1 + cg + c);
        float4 r;
        r.x = (w0 * a.x + w1 * bb.x) * inv;
        r.y = (w0 * a.y + w1 * bb.y) * inv;
        r.z = (w0 * a.z + w1 * bb.z) * inv;
        r.w = (w0 * a.w + w1 * bb.w) * inv;
        *reinterpret_cast<float4*>(og + cg + c) = r;
    }
}

// ---------------------------------------------------------------------------
extern "C" void kernel_launch(void* const* d_in, const int* in_sizes, int n_in,
                              void* d_out, int out_size) {
    const float* x  = (const float*)d_in[0];
    const float* Wq = (const float*)d_in[1];
    const float* bq = (const float*)d_in[2];
    const float* Wk = (const float*)d_in[3];
    const float* bk = (const float*)d_in[4];
    const float* Wv = (const float*)d_in[5];
    const float* bv = (const float*)d_in[6];
    float* out = (float*)d_out;

    split_w_kernel<<<(3 * CDIM * HDIM) / 256, 256>>>(Wq, Wk, Wv);

    cudaFuncSetAttribute(fused_proj_kernel,
                         cudaFuncAttributeMaxDynamicSharedMemorySize, F_SMEM);
    fused_proj_kernel<<<dim3((BT / FM) * 2), 256, F_SMEM>>>(x, bq, bk, bv);

    cudaFuncSetAttribute(attn_kernel,
                         cudaFuncAttributeMaxDynamicSharedMemorySize, A_SMEM);
    attn_kernel<<<dim3(48 * BATCH), 256, A_SMEM>>>(out);

    reduce_kernel<<<512, 256>>>(out);
}